// round 1
// baseline (speedup 1.0000x reference)
#include <cuda_runtime.h>
#include <cuda_bf16.h>

// Problem constants (fixed by the reference setup_inputs)
#define BATCH 4
#define CH    256
#define HH    64
#define WW    64
#define NROI  256
#define PP    7        // pooled size == part size
#define SS    4        // samples per bin edge
#define SPATIAL_SCALE 0.125f
#define TRANS_STD     0.1f

// 16 MB NHWC scratch: g_nhwc[((b*H + y)*W + x)*C + c]
__device__ float g_nhwc[BATCH * HH * WW * CH];

// ---------------------------------------------------------------------------
// Kernel 1: NCHW -> NHWC transpose, smem-tiled, coalesced on both sides.
// Block: 32x32 threads. Tile over (c, w) for a fixed (b, h).
// Grid: (W/32, C/32, B*H)
// ---------------------------------------------------------------------------
__global__ __launch_bounds__(1024) void nchw_to_nhwc_kernel(const float* __restrict__ data) {
    __shared__ float tile[32][33];   // +1 pad: no bank conflicts on transpose read
    const int bh = blockIdx.z;
    const int b  = bh / HH;
    const int h  = bh % HH;
    const int c0 = blockIdx.y * 32;
    const int w0 = blockIdx.x * 32;
    const int tx = threadIdx.x;
    const int ty = threadIdx.y;

    // coalesced read: consecutive tx -> consecutive w
    tile[ty][tx] = data[((b * CH + (c0 + ty)) * HH + h) * WW + (w0 + tx)];
    __syncthreads();
    // coalesced write: consecutive tx -> consecutive c
    g_nhwc[((b * HH + h) * WW + (w0 + ty)) * CH + (c0 + tx)] = tile[tx][ty];
}

// ---------------------------------------------------------------------------
// Kernel 2: deformable RoI pooling on NHWC data.
// Each 64-thread group handles one (roi, ph, pw) bin; thread t owns channels
// [4t, 4t+4) as a float4. Blocks of 256 threads = 4 bins per block.
// Per-warp corner loads are 32 consecutive float4 -> one 512B transaction.
// ---------------------------------------------------------------------------
__global__ __launch_bounds__(256) void deform_roi_pool_kernel(
    const float* __restrict__ rois,
    const float* __restrict__ offset,
    float* __restrict__ out)
{
    const int bin = blockIdx.x * 4 + (threadIdx.x >> 6);   // 0 .. N*P*P-1
    const int c4  = threadIdx.x & 63;                       // channel quad id

    const int n  = bin / (PP * PP);
    const int r  = bin % (PP * PP);
    const int ph = r / PP;
    const int pw = r % PP;

    // RoI geometry (identical math to the reference; rintf == round-half-even)
    const float* roi = rois + n * 5;
    const int   b      = (int)roi[0];
    const float roi_sw = rintf(roi[1]) * SPATIAL_SCALE - 0.5f;
    const float roi_sh = rintf(roi[2]) * SPATIAL_SCALE - 0.5f;
    const float roi_ew = (rintf(roi[3]) + 1.0f) * SPATIAL_SCALE - 0.5f;
    const float roi_eh = (rintf(roi[4]) + 1.0f) * SPATIAL_SCALE - 0.5f;
    const float roi_w  = fmaxf(roi_ew - roi_sw, 0.1f);
    const float roi_h  = fmaxf(roi_eh - roi_sh, 0.1f);
    const float bin_w  = roi_w / (float)PP;
    const float bin_h  = roi_h / (float)PP;
    const float sub_w  = bin_w / (float)SS;
    const float sub_h  = bin_h / (float)SS;

    // part_h == ph, part_w == pw since PP == PART
    const float tx_off = offset[(n * 2 + 0) * (PP * PP) + r] * TRANS_STD;
    const float ty_off = offset[(n * 2 + 1) * (PP * PP) + r] * TRANS_STD;

    const float wstart = (float)pw * bin_w + roi_sw + tx_off * roi_w;
    const float hstart = (float)ph * bin_h + roi_sh + ty_off * roi_h;

    const float4* __restrict__ base =
        reinterpret_cast<const float4*>(g_nhwc) + (size_t)b * (HH * WW * (CH / 4));

    float4 acc = make_float4(0.f, 0.f, 0.f, 0.f);
    int count = 0;

    #pragma unroll
    for (int sh = 0; sh < SS; sh++) {
        const float hcoord = hstart + (float)sh * sub_h;
        #pragma unroll
        for (int sw = 0; sw < SS; sw++) {
            const float wcoord = wstart + (float)sw * sub_w;
            const bool valid = (wcoord > -0.5f) && (wcoord < (float)WW - 0.5f) &&
                               (hcoord > -0.5f) && (hcoord < (float)HH - 0.5f);
            if (!valid) continue;
            count++;

            const float wc = fminf(fmaxf(wcoord, 0.0f), (float)(WW - 1));
            const float hc = fminf(fmaxf(hcoord, 0.0f), (float)(HH - 1));
            const int x0 = (int)floorf(wc);
            const int y0 = (int)floorf(hc);
            const int x1 = min(x0 + 1, WW - 1);
            const int y1 = min(y0 + 1, HH - 1);
            const float dx = wc - (float)x0;
            const float dy = hc - (float)y0;

            const float w00 = (1.0f - dx) * (1.0f - dy);
            const float w01 = dx * (1.0f - dy);
            const float w10 = (1.0f - dx) * dy;
            const float w11 = dx * dy;

            const int row0 = y0 * WW;
            const int row1 = y1 * WW;
            const float4 v00 = base[(row0 + x0) * (CH / 4) + c4];
            const float4 v01 = base[(row0 + x1) * (CH / 4) + c4];
            const float4 v10 = base[(row1 + x0) * (CH / 4) + c4];
            const float4 v11 = base[(row1 + x1) * (CH / 4) + c4];

            acc.x += w00 * v00.x + w01 * v01.x + w10 * v10.x + w11 * v11.x;
            acc.y += w00 * v00.y + w01 * v01.y + w10 * v10.y + w11 * v11.y;
            acc.z += w00 * v00.z + w01 * v01.z + w10 * v10.z + w11 * v11.z;
            acc.w += w00 * v00.w + w01 * v01.w + w10 * v10.w + w11 * v11.w;
        }
    }

    const float inv = (count > 0) ? (1.0f / (float)count) : 0.0f;

    // out[n][c][ph][pw], c = 4*c4 .. 4*c4+3
    const int c = c4 * 4;
    float* o = out + ((size_t)n * CH + c) * (PP * PP) + r;
    o[0 * PP * PP] = acc.x * inv;
    o[1 * PP * PP] = acc.y * inv;
    o[2 * PP * PP] = acc.z * inv;
    o[3 * PP * PP] = acc.w * inv;
}

extern "C" void kernel_launch(void* const* d_in, const int* in_sizes, int n_in,
                              void* d_out, int out_size) {
    const float* data   = (const float*)d_in[0];   // [4,256,64,64]
    const float* rois   = (const float*)d_in[1];   // [256,5]
    const float* offset = (const float*)d_in[2];   // [256,2,7,7]
    float* out = (float*)d_out;                    // [256,256,7,7]

    dim3 tb(32, 32);
    dim3 tg(WW / 32, CH / 32, BATCH * HH);
    nchw_to_nhwc_kernel<<<tg, tb>>>(data);

    const int nbins = NROI * PP * PP;              // 12544, divisible by 4
    deform_roi_pool_kernel<<<nbins / 4, 256>>>(rois, offset, out);
}

// round 2
// speedup vs baseline: 1.7585x; 1.7585x over previous
#include <cuda_runtime.h>
#include <cuda_bf16.h>

// Problem constants (fixed by the reference setup_inputs)
#define BATCH 4
#define CH    256
#define HH    64
#define WW    64
#define NROI  256
#define PP    7        // pooled size == part size
#define SS    4        // samples per bin edge
#define SPATIAL_SCALE 0.125f
#define TRANS_STD     0.1f

// 16 MB NHWC scratch: g_nhwc[((b*H + y)*W + x)*C + c]
__device__ float g_nhwc[BATCH * HH * WW * CH];

// ---------------------------------------------------------------------------
// Kernel 1: NCHW -> NHWC transpose, smem-tiled, 4 elems/thread (MLP=4).
// Block (32,8), tile 32c x 32w per (b,h). Grid: (W/32, C/32, B*H)
// ---------------------------------------------------------------------------
__global__ __launch_bounds__(256) void nchw_to_nhwc_kernel(const float* __restrict__ data) {
    __shared__ float tile[32][33];
    const int bh = blockIdx.z;
    const int b  = bh / HH;
    const int h  = bh % HH;
    const int c0 = blockIdx.y * 32;
    const int w0 = blockIdx.x * 32;
    const int tx = threadIdx.x;
    const int ty = threadIdx.y;

    // 4 independent coalesced loads (consecutive tx -> consecutive w)
    float v0 = data[((b * CH + (c0 + ty +  0)) * HH + h) * WW + (w0 + tx)];
    float v1 = data[((b * CH + (c0 + ty +  8)) * HH + h) * WW + (w0 + tx)];
    float v2 = data[((b * CH + (c0 + ty + 16)) * HH + h) * WW + (w0 + tx)];
    float v3 = data[((b * CH + (c0 + ty + 24)) * HH + h) * WW + (w0 + tx)];
    tile[ty +  0][tx] = v0;
    tile[ty +  8][tx] = v1;
    tile[ty + 16][tx] = v2;
    tile[ty + 24][tx] = v3;
    __syncthreads();
    // coalesced writes: consecutive tx -> consecutive c; smem read conflict-free (33 pad)
    #pragma unroll
    for (int i = 0; i < 4; i++) {
        g_nhwc[((b * HH + h) * WW + (w0 + ty + 8 * i)) * CH + (c0 + tx)] = tile[tx][ty + 8 * i];
    }
}

// ---------------------------------------------------------------------------
// Kernel 2: deformable RoI pooling, separable dedup'd bilinear weights.
// One block = one (roi n, ph) row: 7 bins (pw) x 64 channel-quad threads = 448.
// Phase 1: one leader/bin collapses the 4x4 samples into wx[4], wy[4], count.
// Phase 2: each thread loads each distinct cell ONCE (float4 over 4 channels)
//          and FMAs; result staged in smem.
// Phase 3: near-coalesced writes of the whole (n, ph) output row.
// ---------------------------------------------------------------------------
struct BinInfo {
    float wx[4];
    float wy[4];
    float inv;
    int xbase, ybase, b;
};

__global__ __launch_bounds__(448) void deform_roi_pool_kernel(
    const float* __restrict__ rois,
    const float* __restrict__ offset,
    float* __restrict__ out)
{
    __shared__ BinInfo sbin[PP];
    __shared__ float4  sm4[PP * 64];   // [pw][c4] result staging

    const int ph = blockIdx.x;          // 0..6
    const int n  = blockIdx.y;          // 0..255
    const int tid   = threadIdx.x;
    const int group = tid >> 6;         // pw, 0..6
    const int c4    = tid & 63;         // channel quad

    // ---------------- Phase 1: per-bin separable weights (leader threads) ----
    if (c4 == 0) {
        const int pw = group;
        const int r  = ph * PP + pw;
        const float* roi = rois + n * 5;
        const int   b      = (int)roi[0];
        const float roi_sw = rintf(roi[1]) * SPATIAL_SCALE - 0.5f;
        const float roi_sh = rintf(roi[2]) * SPATIAL_SCALE - 0.5f;
        const float roi_ew = (rintf(roi[3]) + 1.0f) * SPATIAL_SCALE - 0.5f;
        const float roi_eh = (rintf(roi[4]) + 1.0f) * SPATIAL_SCALE - 0.5f;
        const float roi_w  = fmaxf(roi_ew - roi_sw, 0.1f);
        const float roi_h  = fmaxf(roi_eh - roi_sh, 0.1f);
        const float bin_w  = roi_w / (float)PP;
        const float bin_h  = roi_h / (float)PP;
        const float sub_w  = bin_w / (float)SS;
        const float sub_h  = bin_h / (float)SS;

        const float tx_off = offset[(n * 2 + 0) * (PP * PP) + r] * TRANS_STD;
        const float ty_off = offset[(n * 2 + 1) * (PP * PP) + r] * TRANS_STD;

        const float wstart = (float)pw * bin_w + roi_sw + tx_off * roi_w;
        const float hstart = (float)ph * bin_h + roi_sh + ty_off * roi_h;

        // --- x direction ---
        float lwx[4] = {0.f, 0.f, 0.f, 0.f};
        int cw = 0, xb = 0;
        bool xset = false;
        #pragma unroll
        for (int s = 0; s < SS; s++) {
            const float wcoord = wstart + (float)s * sub_w;
            if (wcoord > -0.5f && wcoord < (float)WW - 0.5f) {
                cw++;
                const float wc = fminf(fmaxf(wcoord, 0.0f), (float)(WW - 1));
                const int x0 = (int)floorf(wc);
                if (!xset) { xb = x0; xset = true; }
                const float dx = wc - (float)x0;
                const int o0 = x0 - xb;
                const int o1 = min(x0 + 1, WW - 1) - xb;
                #pragma unroll
                for (int k = 0; k < 4; k++) {
                    lwx[k] += (o0 == k ? 1.0f - dx : 0.0f) + (o1 == k ? dx : 0.0f);
                }
            }
        }
        // --- y direction ---
        float lwy[4] = {0.f, 0.f, 0.f, 0.f};
        int chh = 0, yb = 0;
        bool yset = false;
        #pragma unroll
        for (int s = 0; s < SS; s++) {
            const float hcoord = hstart + (float)s * sub_h;
            if (hcoord > -0.5f && hcoord < (float)HH - 0.5f) {
                chh++;
                const float hc = fminf(fmaxf(hcoord, 0.0f), (float)(HH - 1));
                const int y0 = (int)floorf(hc);
                if (!yset) { yb = y0; yset = true; }
                const float dy = hc - (float)y0;
                const int o0 = y0 - yb;
                const int o1 = min(y0 + 1, HH - 1) - yb;
                #pragma unroll
                for (int k = 0; k < 4; k++) {
                    lwy[k] += (o0 == k ? 1.0f - dy : 0.0f) + (o1 == k ? dy : 0.0f);
                }
            }
        }

        const int cnt = cw * chh;
        BinInfo bi;
        #pragma unroll
        for (int k = 0; k < 4; k++) { bi.wx[k] = lwx[k]; bi.wy[k] = lwy[k]; }
        bi.inv   = (cnt > 0) ? (1.0f / (float)cnt) : 0.0f;
        bi.xbase = xb;
        bi.ybase = yb;
        bi.b     = b;
        sbin[group] = bi;
    }
    __syncthreads();

    // ---------------- Phase 2: dedup'd gather + FMA --------------------------
    {
        const BinInfo bi = sbin[group];
        const float4* __restrict__ base =
            reinterpret_cast<const float4*>(g_nhwc) + (size_t)bi.b * (HH * WW * (CH / 4));

        float4 acc = make_float4(0.f, 0.f, 0.f, 0.f);
        #pragma unroll
        for (int yi = 0; yi < 4; yi++) {
            const float wyv = bi.wy[yi];
            if (wyv == 0.0f) continue;
            const float4* __restrict__ rowp =
                base + ((bi.ybase + yi) * WW + bi.xbase) * (CH / 4) + c4;
            float4 racc = make_float4(0.f, 0.f, 0.f, 0.f);
            #pragma unroll
            for (int xi = 0; xi < 4; xi++) {
                const float wxv = bi.wx[xi];
                if (wxv == 0.0f) continue;
                const float4 v = rowp[xi * (CH / 4)];
                racc.x += wxv * v.x;
                racc.y += wxv * v.y;
                racc.z += wxv * v.z;
                racc.w += wxv * v.w;
            }
            acc.x += wyv * racc.x;
            acc.y += wyv * racc.y;
            acc.z += wyv * racc.z;
            acc.w += wyv * racc.w;
        }
        acc.x *= bi.inv; acc.y *= bi.inv; acc.z *= bi.inv; acc.w *= bi.inv;
        sm4[group * 64 + c4] = acc;     // [pw][c4], STS.128 conflict-free
    }
    __syncthreads();

    // ---------------- Phase 3: near-coalesced output writes -------------------
    // out[n][c][ph][pw] = outbase + c*49 + pw ; smem holds sm[(pw)*256 + c]
    {
        const float* sm = reinterpret_cast<const float*>(sm4);
        const size_t outbase = (size_t)n * (CH * PP * PP) + (size_t)ph * PP;
        #pragma unroll
        for (int k = 0; k < 4; k++) {
            const int i  = tid + k * 448;      // 0 .. 1791
            const int c  = i / 7;
            const int pw = i % 7;
            out[outbase + (size_t)c * (PP * PP) + pw] = sm[pw * CH + c];
        }
    }
}

extern "C" void kernel_launch(void* const* d_in, const int* in_sizes, int n_in,
                              void* d_out, int out_size) {
    const float* data   = (const float*)d_in[0];   // [4,256,64,64]
    const float* rois   = (const float*)d_in[1];   // [256,5]
    const float* offset = (const float*)d_in[2];   // [256,2,7,7]
    float* out = (float*)d_out;                    // [256,256,7,7]

    dim3 tb(32, 8);
    dim3 tg(WW / 32, CH / 32, BATCH * HH);
    nchw_to_nhwc_kernel<<<tg, tb>>>(data);

    dim3 pg(PP, NROI);                             // (ph, n)
    deform_roi_pool_kernel<<<pg, 448>>>(rois, offset, out);
}